// round 10
// baseline (speedup 1.0000x reference)
#include <cuda_runtime.h>

#define SS   16
#define IND  128
#define OUTD 64
#define ED   32
#define OSTR 160     // output row: [x(64) | h_prime(64) | h_edge(32)]
#define MT   32      // nodes per block
#define NTH  256
#define RPAD 132     // padded smem row (floats), 16B-aligned, conflict-free
#define PF   4

// ---- device-global constants (allocation-free) ----
__device__ float g_w2a[IND];    // W2 @ a_n
__device__ float g_wax[IND];    // W  @ a_x

// ---------------------------------------------------------------------------
__global__ void prelude(const float* __restrict__ W, const float* __restrict__ W2,
                        const float* __restrict__ a) {
    int k = threadIdx.x;                        // 0..127
    float s1 = 0.f, s2 = 0.f;
#pragma unroll
    for (int d = 0; d < OUTD; ++d) {
        s1 = fmaf(W [k * OUTD + d], a[d],        s1);
        s2 = fmaf(W2[k * OUTD + d], a[OUTD + d], s2);
    }
    g_wax[k] = s1;
    g_w2a[k] = s2;
}

// ---------------------------------------------------------------------------
// Fused: stage input -> warp-per-node attention with BATCHED score reduce +
// classic softmax (no per-step serial chain) -> in-block dual GEMM.
// ---------------------------------------------------------------------------
__global__ __launch_bounds__(NTH, 3)
void fused(const float* __restrict__ input, const float* __restrict__ neigh,
           const float* __restrict__ ee, const float* __restrict__ a,
           const float* __restrict__ W, const float* __restrict__ W2,
           float* __restrict__ out, int N) {
    __shared__ float s_in [MT * RPAD];          // 16.9 KB
    __shared__ float s_agg[MT * RPAD];          // 16.9 KB

    const int t  = threadIdx.x;
    const int m0 = blockIdx.x * MT;
    const int nv = min(MT, N - m0);

    // ---- stage input tile (coalesced float4) ----
    for (int i = t; i < MT * (IND / 4); i += NTH) {
        int m = i >> 5, j = i & 31;
        float4 v = make_float4(0.f, 0.f, 0.f, 0.f);
        if (m < nv) v = ((const float4*)input)[(size_t)(m0 + m) * 32 + j];
        ((float4*)(s_in + m * RPAD))[j] = v;
    }
    __syncthreads();

    // ================= attention phase (warp per node, 4 nodes/warp) ========
    {
        const int w = t >> 5, lane = t & 31;
        const float4 w2a4 = ((const float4*)g_w2a)[lane];
        const float4 wax4 = ((const float4*)g_wax)[lane];
        const float  ae   = a[2 * OUTD + lane];

        for (int j = 0; j < 4; ++j) {
            const int local = w * 4 + j;
            const int n     = m0 + local;
            if (n >= N) break;                  // warp-uniform

            const float4* nb = (const float4*)neigh + (size_t)n * (SS * IND / 4);
            const float*  eb = ee + (size_t)n * (SS * ED);

            // sx = input_row . (W @ a_x)
            float4 xi = ((const float4*)(s_in + local * RPAD))[lane];
            float p = xi.x * wax4.x;
            p = fmaf(xi.y, wax4.y, p);
            p = fmaf(xi.z, wax4.z, p);
            p = fmaf(xi.w, wax4.w, p);
#pragma unroll
            for (int o = 16; o; o >>= 1) p += __shfl_xor_sync(0xffffffffu, p, o);
            const float sx = p;

            // ---- phase A: per-lane score partials for all 16 neighbors ----
            float part[SS], ev[SS];
            float4 v[PF];
#pragma unroll
            for (int i = 0; i < PF; ++i) v[i] = nb[i * (IND / 4) + lane];
#pragma unroll
            for (int s = 0; s < SS; ++s) {
                ev[s] = eb[s * ED + lane];
                float4 cv = v[s & (PF - 1)];
                if (s + PF < SS) v[s & (PF - 1)] = nb[(s + PF) * (IND / 4) + lane];
                float q = cv.x * w2a4.x;
                q = fmaf(cv.y, w2a4.y, q);
                q = fmaf(cv.z, w2a4.z, q);
                q = fmaf(cv.w, w2a4.w, q);
                part[s] = fmaf(ev[s], ae, q);
            }

            // ---- batched butterfly reduce: 16 values -> lane 2s holds s ----
            {
                int off = 16;
#pragma unroll
                for (int n2 = 8; n2 >= 1; n2 >>= 1, off >>= 1) {
                    const bool hi = (lane & off) != 0;
#pragma unroll
                    for (int s2 = 0; s2 < n2; ++s2) {
                        float send = hi ? part[s2] : part[s2 + n2];
                        float keep = hi ? part[s2 + n2] : part[s2];
                        part[s2] = keep + __shfl_xor_sync(0xffffffffu, send, off);
                    }
                }
                part[0] += __shfl_xor_sync(0xffffffffu, part[0], 1);
            }

            // ---- classic softmax on distributed scores (s = lane>>1) ----
            float sc = part[0] + sx;
            sc = sc > 0.f ? sc : 0.8f * sc;     // leaky relu
            float mx = sc;
#pragma unroll
            for (int o = 16; o; o >>= 1)
                mx = fmaxf(mx, __shfl_xor_sync(0xffffffffu, mx, o));
            float e = __expf(sc - mx);
            float den = e;
#pragma unroll
            for (int o = 16; o >= 2; o >>= 1)
                den += __shfl_xor_sync(0xffffffffu, den, o);
            const float att = e / den;          // lane 2s (and 2s+1) hold att_s

            // ---- phase B: pure-FMA aggregation (neigh re-read, L2-hot) ----
            float4 agg = make_float4(0.f, 0.f, 0.f, 0.f);
            float  he  = 0.f;
#pragma unroll
            for (int i = 0; i < PF; ++i) v[i] = nb[i * (IND / 4) + lane];
#pragma unroll
            for (int s = 0; s < SS; ++s) {
                float as = __shfl_sync(0xffffffffu, att, 2 * s);
                float4 cv = v[s & (PF - 1)];
                if (s + PF < SS) v[s & (PF - 1)] = nb[(s + PF) * (IND / 4) + lane];
                agg.x = fmaf(as, cv.x, agg.x);
                agg.y = fmaf(as, cv.y, agg.y);
                agg.z = fmaf(as, cv.z, agg.z);
                agg.w = fmaf(as, cv.w, agg.w);
                he    = fmaf(as, ev[s], he);
            }

            ((float4*)(s_agg + local * RPAD))[lane] = agg;
            out[(size_t)n * OSTR + 2 * OUTD + lane] = he;   // h_edge (normalized)
        }
    }
    __syncthreads();

    // ================= dual GEMM phase ======================================
    // 32 rows x 128 output cols: cols 0..63 = s_in@W, 64..127 = s_agg@W2.
    {
        const int cg  = t & 31, mg = t >> 5;
        const int c0g = cg * 4;
        const float* wp;
        const float* xb;
        if (c0g < OUTD) { wp = W  + c0g;          xb = s_in  + mg * 4 * RPAD; }
        else            { wp = W2 + (c0g - OUTD); xb = s_agg + mg * 4 * RPAD; }

        float acc[4][4];
#pragma unroll
        for (int r = 0; r < 4; ++r)
#pragma unroll
            for (int c = 0; c < 4; ++c) acc[r][c] = 0.f;

        float4 wv = *(const float4*)wp;         // k = 0 prefetch
#pragma unroll 4
        for (int k = 0; k < IND; ++k) {
            float4 wn;
            if (k + 1 < IND) wn = *(const float4*)(wp + (k + 1) * OUTD);
            float xv[4];
#pragma unroll
            for (int r = 0; r < 4; ++r) xv[r] = xb[r * RPAD + k];   // LDS broadcast
#pragma unroll
            for (int r = 0; r < 4; ++r) {
                acc[r][0] = fmaf(xv[r], wv.x, acc[r][0]);
                acc[r][1] = fmaf(xv[r], wv.y, acc[r][1]);
                acc[r][2] = fmaf(xv[r], wv.z, acc[r][2]);
                acc[r][3] = fmaf(xv[r], wv.w, acc[r][3]);
            }
            wv = wn;
        }

#pragma unroll
        for (int r = 0; r < 4; ++r) {
            int m = mg * 4 + r;
            if (m < nv)
                *(float4*)(out + (size_t)(m0 + m) * OSTR + c0g) = *(float4*)acc[r];
        }
    }
}

// ---------------------------------------------------------------------------
extern "C" void kernel_launch(void* const* d_in, const int* in_sizes, int n_in,
                              void* d_out, int out_size) {
    const float* input = (const float*)d_in[0];
    const float* neigh = (const float*)d_in[1];
    const float* ee    = (const float*)d_in[2];
    const float* W     = (const float*)d_in[3];
    const float* W2    = (const float*)d_in[4];
    const float* a     = (const float*)d_in[5];
    float* out = (float*)d_out;

    const int N = in_sizes[0] / IND;            // 50000

    prelude<<<1, 128>>>(W, W2, a);
    fused<<<(N + MT - 1) / MT, NTH>>>(input, neigh, ee, a, W, W2, out, N);
}